// round 13
// baseline (speedup 1.0000x reference)
#include <cuda_runtime.h>
#include <cstdint>

// Chebyshev-KAN: out[b] = sum_d sum_{k=0..8} coeff[d*9+k] * T_k(x[b,d])
// x: (16384, 512) f32; coeff: (4608,) f32; out: (16384,) f32.
//
// R13: cp.async deep pipeline. Warp = 64-dim slice (monomial coeffs in 9
// packed-f32x2 regs). Each warp copies its 1KB slice of each 4-row group
// into a PRIVATE 5-slot smem ring via cp.async.cg (2 instrs/group,
// commit_group / wait_group 3 / __syncwarp -- no CTA barriers in the loop).
// Depth-5 per-warp pipeline keeps ~4KB/warp in flight (~128KB/SM), 7x the
// Little's-law requirement for full DRAM bandwidth; register pressure stays
// low because x never lives in registers. Compute: LDS.64 + packed-f32x2
// Horner + 9-shuffle fold tree; in-CTA smem partials, single trailing
// __syncthreads, direct out[] stores. Single kernel.

#define DIM      512
#define NDEG     9
#define THREADS  256
#define TILE     4
#define NGROUPS  4096          // 16384 / 4
#define GRID1    592           // 148 SMs x 4 CTAs, single wave
#define MAXIT    7             // ceil(4096/592)
#define NBUF     5             // smem ring slots per warp (1KB each)
#define SSTRIDE  9

typedef unsigned long long ull;

__device__ __forceinline__ ull pack2(float lo, float hi) {
    ull r; asm("mov.b64 %0, {%1, %2};" : "=l"(r) : "f"(lo), "f"(hi)); return r;
}
__device__ __forceinline__ void unpack2(ull v, float& lo, float& hi) {
    asm("mov.b64 {%0, %1}, %2;" : "=f"(lo), "=f"(hi) : "l"(v));
}
__device__ __forceinline__ ull fma2(ull a, ull b, ull c) {
    ull r; asm("fma.rn.f32x2 %0, %1, %2, %3;" : "=l"(r) : "l"(a), "l"(b), "l"(c)); return r;
}

// Chebyshev coeffs c[0..8] -> monomial coeffs a[0..8].
__device__ __forceinline__ void cheb2mono(const float* __restrict__ c, float* a) {
    a[8] = 128.0f * c[8];
    a[7] =  64.0f * c[7];
    a[6] = fmaf(-256.0f, c[8], 32.0f * c[6]);
    a[5] = fmaf(-112.0f, c[7], 16.0f * c[5]);
    a[4] = fmaf(160.0f, c[8], fmaf(-48.0f, c[6], 8.0f * c[4]));
    a[3] = fmaf( 56.0f, c[7], fmaf(-20.0f, c[5], 4.0f * c[3]));
    a[2] = fmaf(-32.0f, c[8], fmaf(18.0f, c[6], fmaf(-8.0f, c[4], 2.0f * c[2])));
    a[1] = fmaf( -7.0f, c[7], fmaf( 5.0f, c[5], fmaf(-3.0f, c[3], c[1])));
    a[0] = ((c[0] - c[2]) + (c[4] - c[6])) + c[8];
}

// Issue this warp's slice of group g into ring slot (2x cp.async.cg 16B).
// Lane j of instr pair covers row (2*pair + lane/16), bytes (lane%16)*16.
__device__ __forceinline__ void issue_group(const float* __restrict__ x,
                                            uint32_t slot_saddr,
                                            int g, int s, int lane) {
    if (g < NGROUPS) {
        const int rhalf = lane >> 4;           // 0/1 within pair
        const int c16   = lane & 15;           // 16B chunk within 256B slice
        const float* src0 = x + (size_t)(TILE * g + rhalf) * DIM + s * 64 + c16 * 4;
        uint32_t dst0 = slot_saddr + lane * 16;
        asm volatile("cp.async.cg.shared.global [%0], [%1], 16;"
                     :: "r"(dst0), "l"(src0) : "memory");
        const float* src1 = src0 + 2 * DIM;    // rows 2,3
        uint32_t dst1 = dst0 + 512;
        asm volatile("cp.async.cg.shared.global [%0], [%1], 16;"
                     :: "r"(dst1), "l"(src1) : "memory");
    }
    asm volatile("cp.async.commit_group;" ::: "memory");
}

// Compute 4 rows of slice s from smem slot, fold, store smem partial.
__device__ __forceinline__ void do_group(const float2* __restrict__ xs,
                                         const ull* A,
                                         float* __restrict__ s_part,
                                         int s, int slotidx, int lane) {
    float acc[TILE];
    #pragma unroll
    for (int r = 0; r < TILE; ++r) {
        float2 v = xs[r * 32 + lane];          // LDS.64, conflict-free
        ull xp = pack2(v.x, v.y);
        ull p = A[8];
        #pragma unroll
        for (int k = 7; k >= 0; --k) p = fma2(p, xp, A[k]);
        float lo, hi; unpack2(p, lo, hi);
        acc[r] = lo + hi;
    }
    // fold tree: 9 shuffles reduce 4 rows; lane bits (4,3) -> row
    float v0, v1;
    {
        float lo = acc[0] + __shfl_xor_sync(0xffffffffu, acc[0], 16);
        float hi = acc[1] + __shfl_xor_sync(0xffffffffu, acc[1], 16);
        v0 = (lane & 16) ? hi : lo;
        lo = acc[2] + __shfl_xor_sync(0xffffffffu, acc[2], 16);
        hi = acc[3] + __shfl_xor_sync(0xffffffffu, acc[3], 16);
        v1 = (lane & 16) ? hi : lo;
    }
    float u;
    {
        float lo = v0 + __shfl_xor_sync(0xffffffffu, v0, 8);
        float hi = v1 + __shfl_xor_sync(0xffffffffu, v1, 8);
        u = (lane & 8) ? hi : lo;
    }
    u += __shfl_xor_sync(0xffffffffu, u, 4);
    u += __shfl_xor_sync(0xffffffffu, u, 2);
    u += __shfl_xor_sync(0xffffffffu, u, 1);
    if ((lane & 7) == 0) {
        int rm = 2 * ((lane >> 3) & 1) + ((lane >> 4) & 1);
        s_part[(slotidx * TILE + rm) * SSTRIDE + s] = u;
    }
}

__global__ __launch_bounds__(THREADS, 4)
void kan_cheb_kernel(const float* __restrict__ x,
                     const float* __restrict__ coeff,
                     float* __restrict__ out)
{
    __shared__ __align__(16) float s_x[8][NBUF][256];      // 8 warps x 5KB
    __shared__ float s_part[MAXIT * TILE * SSTRIDE];

    const int tid  = threadIdx.x;
    const int lane = tid & 31;
    const int s    = tid >> 5;            // slice 0..7 (fixed per warp)
    const int d0   = s * 64 + lane * 2;
    const int bid  = blockIdx.x;

    const uint32_t ring = (uint32_t)__cvta_generic_to_shared(&s_x[s][0][0]);

    // ---- prologue: issue first 4 groups' cp.asyncs BEFORE coeff work ----
    #pragma unroll
    for (int b = 0; b < 4; ++b)
        issue_group(x, ring + (uint32_t)(b * 1024), bid + b * GRID1, s, lane);

    // coeff prologue: 18 consecutive floats -> monomial -> packed regs
    float cf[18];
    {
        const float2* c2 = reinterpret_cast<const float2*>(coeff + d0 * NDEG);
        #pragma unroll
        for (int i = 0; i < 9; ++i) { float2 v = c2[i]; cf[2*i] = v.x; cf[2*i+1] = v.y; }
    }
    ull A[9];
    {
        float t0[9], t1[9];
        cheb2mono(cf, t0); cheb2mono(cf + 9, t1);
        #pragma unroll
        for (int k = 0; k < 9; ++k) A[k] = pack2(t0[k], t1[k]);
    }

    // ---- per-warp pipelined loop: wait oldest, refill, compute ----
    int g = bid;
    #pragma unroll
    for (int it = 0; it < MAXIT; ++it, g += GRID1) {
        if (g >= NGROUPS) break;
        asm volatile("cp.async.wait_group 3;" ::: "memory");
        __syncwarp();
        const int slot = it % NBUF;
        // refill: group g+4 goes to slot (it+4)%NBUF (never the compute slot)
        issue_group(x, ring + (uint32_t)(((it + 4) % NBUF) * 1024),
                    g + 4 * GRID1, s, lane);
        do_group(reinterpret_cast<const float2*>(&s_x[s][slot][0]),
                 A, s_part, s, it, lane);
    }

    // ---- in-CTA finalize: one sync; thread (it,rm) sums 8 partials ----
    __syncthreads();
    if (tid < MAXIT * TILE) {
        const int it = tid >> 2;
        const int rm = tid & 3;
        const int gg = bid + it * GRID1;
        if (gg < NGROUPS) {
            const float* p = &s_part[tid * SSTRIDE];
            float r = ((p[0] + p[1]) + (p[2] + p[3])) + ((p[4] + p[5]) + (p[6] + p[7]));
            out[gg * TILE + rm] = r;
        }
    }
}

extern "C" void kernel_launch(void* const* d_in, const int* in_sizes, int n_in,
                              void* d_out, int out_size)
{
    const float* x     = (const float*)d_in[0];
    const float* coeff = (const float*)d_in[1];
    // d_in[2] = degree (int32, fixed at 8) — baked in at compile time.
    float* out = (float*)d_out;

    kan_cheb_kernel<<<GRID1, THREADS>>>(x, coeff, out);
}